// round 12
// baseline (speedup 1.0000x reference)
#include <cuda_runtime.h>
#include <cuda_bf16.h>
#include <math.h>

// ---------------- Problem dims ----------------
#define BB 512
#define TT 512
#define VV 50000
#define EE 100
#define HH 40

typedef unsigned long long u64;

// ---------------- f32x2 packed helpers ----------------
__device__ __forceinline__ u64 f2u2(float x, float y) {
    u64 u; asm("mov.b64 %0, {%1,%2};" : "=l"(u) : "f"(x), "f"(y)); return u;
}
__device__ __forceinline__ u64 fma2(u64 a, u64 b, u64 c) {
    u64 d; asm("fma.rn.f32x2 %0, %1, %2, %3;" : "=l"(d) : "l"(a), "l"(b), "l"(c)); return d;
}
__device__ __forceinline__ u64 add2(u64 a, u64 b) {
    u64 d; asm("add.rn.f32x2 %0, %1, %2;" : "=l"(d) : "l"(a), "l"(b)); return d;
}
__device__ __forceinline__ float2 u2f2(u64 u) {
    float lo, hi; asm("mov.b64 {%0,%1}, %2;" : "=f"(lo), "=f"(hi) : "l"(u));
    return make_float2(lo, hi);
}

// single-MUFU tanh (sm_75+)
__device__ __forceinline__ float tanhA(float x) {
    float y; asm("tanh.approx.f32 %0, %1;" : "=f"(y) : "f"(x)); return y;
}
// sigmoid via tanh identity: sig(x) = 0.5*tanh(x/2) + 0.5  (one MUFU)
__device__ __forceinline__ float sigA(float x) {
    return fmaf(tanhA(0.5f * x), 0.5f, 0.5f);
}

// ---------------- Device scratch ----------------
// gate-packed: [row][dir(2)][unit(40)][4: r,z,n,pad]  -> row stride 320 floats
__device__ __align__(16) float g_embW0[(size_t)VV * 320];
__device__ __align__(16) float g_out0[BB * TT * 80];          // layer0 out, [b][t][fwd40|bwd40]
__device__ __align__(16) float g_gx1[(size_t)BB * TT * 320];  // layer1 input gates, gate-packed
__device__ __align__(16) float g_Wih0T[EE * 240];
__device__ __align__(16) float g_bih0cat[240];
__device__ __align__(16) float g_Wih1T[80 * 240];
__device__ __align__(16) float g_bih1cat[240];
// 4-output gate-owner pack: [dir][f(0..119)][k2(0..19)] u64 pairs
__device__ __align__(16) float g_Whh0P4[2 * 120 * 20 * 2];
__device__ __align__(16) float g_Whh1P4[2 * 120 * 20 * 2];
__device__ __align__(16) float g_fc1WT[320 * 128];
__device__ float g_hf0[BB * HH], g_hb0[BB * HH], g_hf1[BB * HH], g_hb1[BB * HH];
__device__ float g_avgp[BB * 80], g_maxp[BB * 80];
__device__ int g_perm[BB];
__device__ float g_sink[592 * 32];   // per-warp dead-store sink (never read)

// ---------------- Prep: transpose / pack all weights ----------------
__global__ void prep_weights(
    const float* __restrict__ Wih0f, const float* __restrict__ Whh0f,
    const float* __restrict__ bih0f,
    const float* __restrict__ Wih0b, const float* __restrict__ Whh0b,
    const float* __restrict__ bih0b,
    const float* __restrict__ Wih1f, const float* __restrict__ Whh1f,
    const float* __restrict__ bih1f,
    const float* __restrict__ Wih1b, const float* __restrict__ Whh1b,
    const float* __restrict__ bih1b,
    const float* __restrict__ fc1_W)
{
    int g = blockIdx.x * blockDim.x + threadIdx.x;
    int NT = gridDim.x * blockDim.x;
    for (int i = g; i < EE * 240; i += NT) {
        int k = i / 240, j = i % 240;
        g_Wih0T[i] = (j < 120) ? Wih0f[j * EE + k] : Wih0b[(j - 120) * EE + k];
    }
    for (int i = g; i < 80 * 240; i += NT) {
        int k = i / 240, j = i % 240;
        g_Wih1T[i] = (j < 120) ? Wih1f[j * 80 + k] : Wih1b[(j - 120) * 80 + k];
    }
    for (int i = g; i < 240; i += NT) {
        g_bih0cat[i] = (i < 120) ? bih0f[i] : bih0b[i - 120];
        g_bih1cat[i] = (i < 120) ? bih1f[i] : bih1b[i - 120];
    }
    // P4 packs: idx = ((dir*120 + f)*20 + k2)*2 + c  ->  Whh_dir[f*40 + 2*k2 + c]
    for (int i = g; i < 2 * 120 * 20 * 2; i += NT) {
        int c = i & 1;
        int t = i >> 1;
        int k2 = t % 20;
        int f = (t / 20) % 120;
        int dir = t / 2400;
        int src = f * 40 + 2 * k2 + c;
        g_Whh0P4[i] = (dir ? Whh0b : Whh0f)[src];
        g_Whh1P4[i] = (dir ? Whh1b : Whh1f)[src];
    }
    for (int i = g; i < 320 * 128; i += NT) {
        int k = i / 128, q = i % 128;
        g_fc1WT[i] = fc1_W[q * 320 + k];
    }
}

// ---------------- Length sort (descending) for load balance ----------------
__global__ void sort_kernel(const int* __restrict__ lens)
{
    __shared__ int L[BB];
    int b = threadIdx.x;
    int lb = lens[b];
    L[b] = lb;
    __syncthreads();
    int r = 0;
    #pragma unroll 8
    for (int i = 0; i < BB; i++) {
        int li = L[i];
        r += (li > lb) || (li == lb && i < b);
    }
    g_perm[r] = b;
}

// ---------------- embW GEMM: [50000,100] x [100,240] + bias; gate-packed stores ----------------
__global__ void __launch_bounds__(128) embw_kernel(const float* __restrict__ emb)
{
    int tid = threadIdx.x;
    int v0 = blockIdx.x * 32;
    int rows = VV - v0; if (rows > 32) rows = 32;
    __shared__ __align__(16) float Xt[100][36];   // [k][r]

    const float4* xb = (const float4*)(emb + (size_t)v0 * EE);
    for (int idx = tid; idx < 32 * 25; idx += 128) {
        int r = idx / 25, c4 = idx % 25;
        float4 v = (r < rows) ? xb[r * 25 + c4] : make_float4(0.f, 0.f, 0.f, 0.f);
        Xt[4 * c4 + 0][r] = v.x;
        Xt[4 * c4 + 1][r] = v.y;
        Xt[4 * c4 + 2][r] = v.z;
        Xt[4 * c4 + 3][r] = v.w;
    }
    __syncthreads();
    if (tid >= 120) return;
    int j0 = tid, j1 = tid + 120;
    u64 a0[16], a1[16];
    {
        float b0 = g_bih0cat[j0], b1 = g_bih0cat[j1];
        u64 i0 = f2u2(b0, b0), i1 = f2u2(b1, b1);
        #pragma unroll
        for (int i = 0; i < 16; i++) { a0[i] = i0; a1[i] = i1; }
    }
    #pragma unroll 4
    for (int k = 0; k < 100; k++) {
        float w0 = g_Wih0T[k * 240 + j0];
        float w1 = g_Wih0T[k * 240 + j1];
        u64 ww0 = f2u2(w0, w0), ww1 = f2u2(w1, w1);
        const ulonglong2* ap = (const ulonglong2*)(&Xt[k][0]);
        #pragma unroll
        for (int p = 0; p < 8; p++) {
            ulonglong2 a = ap[p];
            a0[2 * p + 0] = fma2(a.x, ww0, a0[2 * p + 0]);
            a0[2 * p + 1] = fma2(a.y, ww0, a0[2 * p + 1]);
            a1[2 * p + 0] = fma2(a.x, ww1, a1[2 * p + 0]);
            a1[2 * p + 1] = fma2(a.y, ww1, a1[2 * p + 1]);
        }
    }
    // gate-packed store: column j0 (dir0) -> off = u*4+g ; column j1 (dir1) -> off+160
    int off0 = (j0 % 40) * 4 + (j0 / 40);
    float* o0 = g_embW0 + (size_t)v0 * 320 + off0;
    #pragma unroll
    for (int i = 0; i < 16; i++) {
        float2 v = u2f2(a0[i]);
        float2 u = u2f2(a1[i]);
        int r = 2 * i;
        if (r < rows)     { o0[(size_t)r * 320] = v.x;       o0[(size_t)r * 320 + 160] = u.x; }
        if (r + 1 < rows) { o0[(size_t)(r + 1) * 320] = v.y; o0[(size_t)(r + 1) * 320 + 160] = u.y; }
    }
}

// ---------------- gx1 GEMM: [valid rows,80] x [80,240] + bias; gate-packed stores ----------------
__global__ void __launch_bounds__(128) gx1_kernel(const int* __restrict__ lens)
{
    int b = blockIdx.x;
    int t0 = blockIdx.y * 32;
    int len = lens[b];
    if (t0 >= len) return;
    int rows = len - t0; if (rows > 32) rows = 32;
    int tid = threadIdx.x;
    __shared__ __align__(16) float Xt[80][36];

    const float4* xb = (const float4*)(g_out0 + ((size_t)b * TT + t0) * 80);
    for (int idx = tid; idx < 32 * 20; idx += 128) {
        int r = idx / 20, c4 = idx % 20;
        float4 v = (r < rows) ? xb[r * 20 + c4] : make_float4(0.f, 0.f, 0.f, 0.f);
        Xt[4 * c4 + 0][r] = v.x;
        Xt[4 * c4 + 1][r] = v.y;
        Xt[4 * c4 + 2][r] = v.z;
        Xt[4 * c4 + 3][r] = v.w;
    }
    __syncthreads();
    if (tid >= 120) return;
    int j0 = tid, j1 = tid + 120;
    u64 a0[16], a1[16];
    {
        float b0 = g_bih1cat[j0], b1 = g_bih1cat[j1];
        u64 i0 = f2u2(b0, b0), i1 = f2u2(b1, b1);
        #pragma unroll
        for (int i = 0; i < 16; i++) { a0[i] = i0; a1[i] = i1; }
    }
    #pragma unroll 4
    for (int k = 0; k < 80; k++) {
        float w0 = g_Wih1T[k * 240 + j0];
        float w1 = g_Wih1T[k * 240 + j1];
        u64 ww0 = f2u2(w0, w0), ww1 = f2u2(w1, w1);
        const ulonglong2* ap = (const ulonglong2*)(&Xt[k][0]);
        #pragma unroll
        for (int p = 0; p < 8; p++) {
            ulonglong2 a = ap[p];
            a0[2 * p + 0] = fma2(a.x, ww0, a0[2 * p + 0]);
            a0[2 * p + 1] = fma2(a.y, ww0, a0[2 * p + 1]);
            a1[2 * p + 0] = fma2(a.x, ww1, a1[2 * p + 0]);
            a1[2 * p + 1] = fma2(a.y, ww1, a1[2 * p + 1]);
        }
    }
    int off0 = (j0 % 40) * 4 + (j0 / 40);
    float* o0 = g_gx1 + ((size_t)b * TT + t0) * 320 + off0;
    #pragma unroll
    for (int i = 0; i < 16; i++) {
        float2 v = u2f2(a0[i]);
        float2 u = u2f2(a1[i]);
        int r = 2 * i;
        if (r < rows)     { o0[(size_t)r * 320] = v.x;       o0[(size_t)r * 320 + 160] = u.x; }
        if (r + 1 < rows) { o0[(size_t)(r + 1) * 320] = v.y; o0[(size_t)(r + 1) * 320 + 160] = u.y; }
    }
}

// ---- shared recurrence step body: split-chain dot, MUFU acts, branch-free stores ----
// P4/Q4: this sub-step's packed gates (float4: r,z,n,pad), reloaded for s+2
#define GRU_CORE(P4, Q4, EBASE, OFF_EXPR, ACT_EXTRA0, ACT_EXTRA1)                           \
    {                                                                                       \
        float4 xg = P4, yg = Q4;                                                            \
        {                                                                                   \
            const float* e_ = (EBASE) + (OFF_EXPR);                                         \
            P4 = *(const float4*)(e_ + 4 * u0);                                             \
            Q4 = *(const float4*)(e_ + 4 * u1c);                                            \
        }                                                                                   \
        u64 a0a = bbu[0], a0b = 0ull;                                                       \
        u64 a1a = bbu[1], a1b = 0ull;                                                       \
        u64 a2a = bbu[2], a2b = 0ull;                                                       \
        u64 a3a = bbu[3], a3b = 0ull;                                                       \
        const ulonglong2* hq = (const ulonglong2*)hsm;                                      \
        _Pragma("unroll")                                                                   \
        for (int q = 0; q < 5; q++) {                                                       \
            ulonglong2 hA = hq[2 * q], hB = hq[2 * q + 1];                                  \
            a0a = fma2(w[0][4*q],   hA.x, a0a); a0a = fma2(w[0][4*q+1], hA.y, a0a);         \
            a0b = fma2(w[0][4*q+2], hB.x, a0b); a0b = fma2(w[0][4*q+3], hB.y, a0b);         \
            a1a = fma2(w[1][4*q],   hA.x, a1a); a1a = fma2(w[1][4*q+1], hA.y, a1a);         \
            a1b = fma2(w[1][4*q+2], hB.x, a1b); a1b = fma2(w[1][4*q+3], hB.y, a1b);         \
            a2a = fma2(w[2][4*q],   hA.x, a2a); a2a = fma2(w[2][4*q+1], hA.y, a2a);         \
            a2b = fma2(w[2][4*q+2], hB.x, a2b); a2b = fma2(w[2][4*q+3], hB.y, a2b);         \
            a3a = fma2(w[3][4*q],   hA.x, a3a); a3a = fma2(w[3][4*q+1], hA.y, a3a);         \
            a3b = fma2(w[3][4*q+2], hB.x, a3b); a3b = fma2(w[3][4*q+3], hB.y, a3b);         \
        }                                                                                   \
        float2 p0 = u2f2(add2(a0a, a0b));                                                   \
        float2 p1 = u2f2(add2(a1a, a1b));                                                   \
        float2 p2 = u2f2(add2(a2a, a2b));                                                   \
        float2 p3 = u2f2(add2(a3a, a3b));                                                   \
        float d0 = p0.x + p0.y;                                                             \
        float d1 = p1.x + p1.y;                                                             \
        float d2 = p2.x + p2.y;                                                             \
        float d3 = p3.x + p3.y;                                                             \
        float s1 = __shfl_sync(FULL, d1, (lane + 8)  & 31);                                 \
        float s2 = __shfl_sync(FULL, d2, (lane + 8)  & 31);                                 \
        float s3 = __shfl_sync(FULL, d2, (lane + 16) & 31);                                 \
        float s4 = __shfl_sync(FULL, d3, (lane + 16) & 31);                                 \
        float zv0 = (lane < 24) ? s1 : s2;                                                  \
        float nv0 = (lane < 16) ? s3 : s4;                                                  \
        {                                                                                   \
            float r = sigA(xg.x + d0);                                                      \
            float z = sigA(xg.y + zv0);                                                     \
            float n = tanhA(fmaf(r, nv0, xg.z));                                            \
            h0 = fmaf(z, h0 - n, n);                                                        \
            hsm[u0] = h0;                                                                   \
            ACT_EXTRA0;                                                                     \
        }                                                                                   \
        {                                                                                   \
            float r = sigA(yg.x + d1);                                                      \
            float z = sigA(yg.y + s2);                                                      \
            float n = tanhA(fmaf(r, s4, yg.z));                                             \
            h1 = fmaf(z, h1 - n, n);                                                        \
            hsm[h1idx] = h1;                                                                \
            ACT_EXTRA1;                                                                     \
        }                                                                                   \
        __syncwarp();                                                                       \
    }

// ---------------- Layer 0: one warp per (batch,dir); unroll-2 distance-2 prefetch ----------------
__global__ void __launch_bounds__(128) gru_layer0(
    const int* __restrict__ text, const int* __restrict__ lens,
    const float* __restrict__ bhh0f, const float* __restrict__ bhh0b)
{
    int wid = threadIdx.x >> 5, lane = threadIdx.x & 31;
    int wgid = blockIdx.x * 4 + wid;
    __shared__ int toks_s[4][TT];
    __shared__ __align__(16) float h_s[4][80];   // [0..39] h, [40..71] dead zone
    if (wgid >= 512) return;
    int* toks = toks_s[wid];
    float* hsm = h_s[wid];
    const unsigned FULL = 0xffffffffu;
    float* sinkp = g_sink + (size_t)wgid * 32 + lane;

    for (int slot = 0; slot < 2; slot++) {
        int c = slot ? (1023 - wgid) : wgid;
        int b = g_perm[c >> 1];
        int dir = c & 1;
        int len = lens[b];

        for (int i = lane; i < len; i += 32) toks[i] = text[b * TT + i];

        u64 w[4][20];
        u64 bbu[4];
        const u64* wp = (const u64*)g_Whh0P4 + (size_t)dir * 120 * 20;
        const float* bhh = dir ? bhh0b : bhh0f;
        #pragma unroll
        for (int m = 0; m < 4; m++) {
            int f = lane + 32 * m;
            if (f < 120) {
                const u64* wf = wp + f * 20;
                #pragma unroll
                for (int k2 = 0; k2 < 20; k2++) w[m][k2] = wf[k2];
                bbu[m] = f2u2(bhh[f], 0.f);
            } else {
                #pragma unroll
                for (int k2 = 0; k2 < 20; k2++) w[m][k2] = 0ull;
                bbu[m] = 0ull;
            }
        }
        hsm[lane] = 0.f;
        if (lane < 16) hsm[32 + lane] = 0.f;
        __syncwarp();

        int t0 = dir ? (len - 1) : 0;
        int td = dir ? -1 : 1;
        const float* embW = g_embW0 + dir * 160;
        int u0 = lane;
        int u1c = 32 + (lane & 7);
        bool two = (lane < 8);
        int h1idx = two ? u1c : (40 + lane);   // branch-free store target

        float4 A4, C4, B4, D4;   // A/C even-step gates (u0/u1), B/D odd-step
        {
            const float* e0 = embW + (size_t)toks[t0] * 320;
            A4 = *(const float4*)(e0 + 4 * u0);
            C4 = *(const float4*)(e0 + 4 * u1c);
            int s1i = (len > 1) ? 1 : 0;
            const float* e1 = embW + (size_t)toks[t0 + s1i * td] * 320;
            B4 = *(const float4*)(e1 + 4 * u0);
            D4 = *(const float4*)(e1 + 4 * u1c);
        }
        float h0 = 0.f, h1 = 0.f;
        float* outb = g_out0 + ((size_t)b * TT + t0) * 80 + dir * 40;
        long ostep = (long)td * 80;

        for (int s = 0; s < len; s += 2) {
            {
                int sp = (s + 2 < len) ? s + 2 : len - 1;
                GRU_CORE(A4, C4, embW, (size_t)toks[t0 + sp * td] * 320,
                         outb[u0] = h0,
                         *(two ? (outb + u1c) : sinkp) = h1)
                outb += ostep;
            }
            if (s + 1 >= len) break;
            {
                int sp = (s + 3 < len) ? s + 3 : len - 1;
                GRU_CORE(B4, D4, embW, (size_t)toks[t0 + sp * td] * 320,
                         outb[u0] = h0,
                         *(two ? (outb + u1c) : sinkp) = h1)
                outb += ostep;
            }
        }
        float* hl = dir ? g_hb0 : g_hf0;
        hl[b * HH + u0] = h0;
        if (two) hl[b * HH + u1c] = h1;
    }
}

// ---------------- Layer 1: same shape, gx precomputed, fused pooling ----------------
__global__ void __launch_bounds__(128) gru_layer1(
    const int* __restrict__ lens,
    const float* __restrict__ bhh1f, const float* __restrict__ bhh1b)
{
    int wid = threadIdx.x >> 5, lane = threadIdx.x & 31;
    int wgid = blockIdx.x * 4 + wid;
    __shared__ __align__(16) float h_s[4][80];
    if (wgid >= 512) return;
    float* hsm = h_s[wid];
    const unsigned FULL = 0xffffffffu;

    for (int slot = 0; slot < 2; slot++) {
        int c = slot ? (1023 - wgid) : wgid;
        int b = g_perm[c >> 1];
        int dir = c & 1;
        int len = lens[b];

        u64 w[4][20];
        u64 bbu[4];
        const u64* wp = (const u64*)g_Whh1P4 + (size_t)dir * 120 * 20;
        const float* bhh = dir ? bhh1b : bhh1f;
        #pragma unroll
        for (int m = 0; m < 4; m++) {
            int f = lane + 32 * m;
            if (f < 120) {
                const u64* wf = wp + f * 20;
                #pragma unroll
                for (int k2 = 0; k2 < 20; k2++) w[m][k2] = wf[k2];
                bbu[m] = f2u2(bhh[f], 0.f);
            } else {
                #pragma unroll
                for (int k2 = 0; k2 < 20; k2++) w[m][k2] = 0ull;
                bbu[m] = 0ull;
            }
        }
        hsm[lane] = 0.f;
        if (lane < 16) hsm[32 + lane] = 0.f;
        __syncwarp();

        int t0 = dir ? (len - 1) : 0;
        int td = dir ? -1 : 1;
        const float* gxb = g_gx1 + ((size_t)b * TT) * 320 + dir * 160;
        int u0 = lane;
        int u1c = 32 + (lane & 7);
        bool two = (lane < 8);
        int h1idx = two ? u1c : (40 + lane);

        float4 A4, C4, B4, D4;
        {
            const float* e0 = gxb + (size_t)t0 * 320;
            A4 = *(const float4*)(e0 + 4 * u0);
            C4 = *(const float4*)(e0 + 4 * u1c);
            int s1i = (len > 1) ? 1 : 0;
            const float* e1 = gxb + (size_t)(t0 + s1i * td) * 320;
            B4 = *(const float4*)(e1 + 4 * u0);
            D4 = *(const float4*)(e1 + 4 * u1c);
        }
        float h0 = 0.f, h1 = 0.f;
        float sum0 = 0.f, max0 = -1e30f, sum1 = 0.f, max1 = -1e30f;

        for (int s = 0; s < len; s += 2) {
            {
                int sp = (s + 2 < len) ? s + 2 : len - 1;
                GRU_CORE(A4, C4, gxb, (size_t)(t0 + sp * td) * 320,
                         { sum0 += h0; max0 = fmaxf(max0, h0); },
                         { sum1 += h1; max1 = fmaxf(max1, h1); })
            }
            if (s + 1 >= len) break;
            {
                int sp = (s + 3 < len) ? s + 3 : len - 1;
                GRU_CORE(B4, D4, gxb, (size_t)(t0 + sp * td) * 320,
                         { sum0 += h0; max0 = fmaxf(max0, h0); },
                         { sum1 += h1; max1 = fmaxf(max1, h1); })
            }
        }
        float inv = __fdividef(1.f, (float)len);
        g_avgp[b * 80 + dir * 40 + u0] = sum0 * inv;
        g_maxp[b * 80 + dir * 40 + u0] = max0;
        float* hl = dir ? g_hb1 : g_hf1;
        hl[b * HH + u0] = h0;
        if (two) {
            g_avgp[b * 80 + dir * 40 + u1c] = sum1 * inv;
            g_maxp[b * 80 + dir * 40 + u1c] = max1;
            hl[b * HH + u1c] = h1;
        }
    }
}

// ---------------- Head: pool_cat -> fc1 -> leaky -> fc2 ----------------
__global__ void __launch_bounds__(128) fc_kernel(
    const float* __restrict__ fc1_b, const float* __restrict__ fc2_W,
    const float* __restrict__ fc2_b, float* __restrict__ out)
{
    int b = blockIdx.x, j = threadIdx.x;
    __shared__ float cat[320];
    for (int i = j; i < 320; i += 128) {
        float v;
        if (i < 40)       v = g_hb1[b * 40 + i];
        else if (i < 80)  v = g_hf1[b * 40 + (i - 40)];
        else if (i < 120) v = g_hb0[b * 40 + (i - 80)];
        else if (i < 160) v = g_hf0[b * 40 + (i - 120)];
        else if (i < 240) v = g_avgp[b * 80 + (i - 160)];
        else              v = g_maxp[b * 80 + (i - 240)];
        cat[i] = v;
    }
    __syncthreads();
    float acc = fc1_b[j];
    #pragma unroll 8
    for (int k = 0; k < 320; k++)
        acc = fmaf(g_fc1WT[k * 128 + j], cat[k], acc);
    float h = (acc >= 0.f) ? acc : 0.01f * acc;
    float p = h * fc2_W[j];
    #pragma unroll
    for (int o = 16; o > 0; o >>= 1) p += __shfl_down_sync(0xffffffffu, p, o);
    __shared__ float red[4];
    if ((j & 31) == 0) red[j >> 5] = p;
    __syncthreads();
    if (j == 0) out[b] = (red[0] + red[1] + red[2] + red[3]) + fc2_b[0];
}

// ---------------- Launch ----------------
extern "C" void kernel_launch(void* const* d_in, const int* in_sizes, int n_in,
                              void* d_out, int out_size)
{
    const int*   text     = (const int*)d_in[0];
    const int*   text_len = (const int*)d_in[1];
    const float* emb      = (const float*)d_in[2];
    const float* Wih0f = (const float*)d_in[3];
    const float* Whh0f = (const float*)d_in[4];
    const float* bih0f = (const float*)d_in[5];
    const float* bhh0f = (const float*)d_in[6];
    const float* Wih0b = (const float*)d_in[7];
    const float* Whh0b = (const float*)d_in[8];
    const float* bih0b = (const float*)d_in[9];
    const float* bhh0b = (const float*)d_in[10];
    const float* Wih1f = (const float*)d_in[11];
    const float* Whh1f = (const float*)d_in[12];
    const float* bih1f = (const float*)d_in[13];
    const float* bhh1f = (const float*)d_in[14];
    const float* Wih1b = (const float*)d_in[15];
    const float* Whh1b = (const float*)d_in[16];
    const float* bih1b = (const float*)d_in[17];
    const float* bhh1b = (const float*)d_in[18];
    const float* fc1_W = (const float*)d_in[19];
    const float* fc1_b = (const float*)d_in[20];
    const float* fc2_W = (const float*)d_in[21];
    const float* fc2_b = (const float*)d_in[22];
    float* out = (float*)d_out;

    prep_weights<<<160, 256>>>(Wih0f, Whh0f, bih0f, Wih0b, Whh0b, bih0b,
                               Wih1f, Whh1f, bih1f, Wih1b, Whh1b, bih1b, fc1_W);
    sort_kernel<<<1, BB>>>(text_len);
    embw_kernel<<<(VV + 31) / 32, 128>>>(emb);
    gru_layer0<<<148, 128>>>(text, text_len, bhh0f, bhh0b);
    gx1_kernel<<<dim3(BB, TT / 32), 128>>>(text_len);
    gru_layer1<<<148, 128>>>(text_len, bhh1f, bhh1b);
    fc_kernel<<<BB, 128>>>(fc1_b, fc2_W, fc2_b, out);
}

// round 13
// speedup vs baseline: 1.3326x; 1.3326x over previous
#include <cuda_runtime.h>
#include <cuda_bf16.h>
#include <math.h>

// ---------------- Problem dims ----------------
#define BB 512
#define TT 512
#define VV 50000
#define EE 100
#define HH 40

typedef unsigned long long u64;

// ---------------- f32x2 packed helpers ----------------
__device__ __forceinline__ u64 f2u2(float x, float y) {
    u64 u; asm("mov.b64 %0, {%1,%2};" : "=l"(u) : "f"(x), "f"(y)); return u;
}
__device__ __forceinline__ u64 fma2(u64 a, u64 b, u64 c) {
    u64 d; asm("fma.rn.f32x2 %0, %1, %2, %3;" : "=l"(d) : "l"(a), "l"(b), "l"(c)); return d;
}
__device__ __forceinline__ u64 add2(u64 a, u64 b) {
    u64 d; asm("add.rn.f32x2 %0, %1, %2;" : "=l"(d) : "l"(a), "l"(b)); return d;
}
__device__ __forceinline__ float2 u2f2(u64 u) {
    float lo, hi; asm("mov.b64 {%0,%1}, %2;" : "=f"(lo), "=f"(hi) : "l"(u));
    return make_float2(lo, hi);
}

// single-MUFU tanh (sm_75+)
__device__ __forceinline__ float tanhA(float x) {
    float y; asm("tanh.approx.f32 %0, %1;" : "=f"(y) : "f"(x)); return y;
}
// sigmoid via tanh identity: sig(x) = 0.5*tanh(x/2) + 0.5  (one MUFU)
__device__ __forceinline__ float sigA(float x) {
    return fmaf(tanhA(0.5f * x), 0.5f, 0.5f);
}

// ---------------- Device scratch ----------------
__device__ __align__(16) float g_embW0[VV * 240];            // layer0 input gates per vocab id
__device__ __align__(16) float g_out0[BB * TT * 80];         // layer0 out, [b][t][fwd40|bwd40]
__device__ __align__(16) float g_gx1[(size_t)BB * TT * 240]; // layer1 precomputed input gates
__device__ __align__(16) float g_Wih0T[EE * 240];
__device__ __align__(16) float g_bih0cat[240];
__device__ __align__(16) float g_Wih1T[80 * 240];
__device__ __align__(16) float g_bih1cat[240];
// 4-output gate-owner pack: [dir][f(0..119)][k2(0..19)] u64 pairs
__device__ __align__(16) float g_Whh0P4[2 * 120 * 20 * 2];
__device__ __align__(16) float g_Whh1P4[2 * 120 * 20 * 2];
__device__ __align__(16) float g_fc1WT[320 * 128];
__device__ float g_hf0[BB * HH], g_hb0[BB * HH], g_hf1[BB * HH], g_hb1[BB * HH];
__device__ float g_avgp[BB * 80], g_maxp[BB * 80];
__device__ int g_perm[BB];
__device__ float g_sink[592 * 32];   // per-warp dead-store sink (never read)

// ---------------- Prep: transpose / pack all weights ----------------
__global__ void prep_weights(
    const float* __restrict__ Wih0f, const float* __restrict__ Whh0f,
    const float* __restrict__ bih0f,
    const float* __restrict__ Wih0b, const float* __restrict__ Whh0b,
    const float* __restrict__ bih0b,
    const float* __restrict__ Wih1f, const float* __restrict__ Whh1f,
    const float* __restrict__ bih1f,
    const float* __restrict__ Wih1b, const float* __restrict__ Whh1b,
    const float* __restrict__ bih1b,
    const float* __restrict__ fc1_W)
{
    int g = blockIdx.x * blockDim.x + threadIdx.x;
    int NT = gridDim.x * blockDim.x;
    for (int i = g; i < EE * 240; i += NT) {
        int k = i / 240, j = i % 240;
        g_Wih0T[i] = (j < 120) ? Wih0f[j * EE + k] : Wih0b[(j - 120) * EE + k];
    }
    for (int i = g; i < 80 * 240; i += NT) {
        int k = i / 240, j = i % 240;
        g_Wih1T[i] = (j < 120) ? Wih1f[j * 80 + k] : Wih1b[(j - 120) * 80 + k];
    }
    for (int i = g; i < 240; i += NT) {
        g_bih0cat[i] = (i < 120) ? bih0f[i] : bih0b[i - 120];
        g_bih1cat[i] = (i < 120) ? bih1f[i] : bih1b[i - 120];
    }
    // P4 packs: idx = ((dir*120 + f)*20 + k2)*2 + c  ->  Whh_dir[f*40 + 2*k2 + c]
    for (int i = g; i < 2 * 120 * 20 * 2; i += NT) {
        int c = i & 1;
        int t = i >> 1;
        int k2 = t % 20;
        int f = (t / 20) % 120;
        int dir = t / 2400;
        int src = f * 40 + 2 * k2 + c;
        g_Whh0P4[i] = (dir ? Whh0b : Whh0f)[src];
        g_Whh1P4[i] = (dir ? Whh1b : Whh1f)[src];
    }
    for (int i = g; i < 320 * 128; i += NT) {
        int k = i / 128, q = i % 128;
        g_fc1WT[i] = fc1_W[q * 320 + k];
    }
}

// ---------------- Length sort (descending) for load balance ----------------
__global__ void sort_kernel(const int* __restrict__ lens)
{
    __shared__ int L[BB];
    int b = threadIdx.x;
    int lb = lens[b];
    L[b] = lb;
    __syncthreads();
    int r = 0;
    #pragma unroll 8
    for (int i = 0; i < BB; i++) {
        int li = L[i];
        r += (li > lb) || (li == lb && i < b);
    }
    g_perm[r] = b;
}

// ---------------- embW GEMM: [50000,100] x [100,240] + bias; 2 cols/thread, 32 rows ----------------
__global__ void __launch_bounds__(128) embw_kernel(const float* __restrict__ emb)
{
    int tid = threadIdx.x;
    int v0 = blockIdx.x * 32;
    int rows = VV - v0; if (rows > 32) rows = 32;
    __shared__ __align__(16) float Xt[100][36];   // [k][r], row = 144B

    const float4* xb = (const float4*)(emb + (size_t)v0 * EE);
    for (int idx = tid; idx < 32 * 25; idx += 128) {
        int r = idx / 25, c4 = idx % 25;
        float4 v = (r < rows) ? xb[r * 25 + c4] : make_float4(0.f, 0.f, 0.f, 0.f);
        Xt[4 * c4 + 0][r] = v.x;
        Xt[4 * c4 + 1][r] = v.y;
        Xt[4 * c4 + 2][r] = v.z;
        Xt[4 * c4 + 3][r] = v.w;
    }
    __syncthreads();
    if (tid >= 120) return;
    int j0 = tid, j1 = tid + 120;
    u64 a0[16], a1[16];
    {
        float b0 = g_bih0cat[j0], b1 = g_bih0cat[j1];
        u64 i0 = f2u2(b0, b0), i1 = f2u2(b1, b1);
        #pragma unroll
        for (int i = 0; i < 16; i++) { a0[i] = i0; a1[i] = i1; }
    }
    #pragma unroll 4
    for (int k = 0; k < 100; k++) {
        float w0 = g_Wih0T[k * 240 + j0];
        float w1 = g_Wih0T[k * 240 + j1];
        u64 ww0 = f2u2(w0, w0), ww1 = f2u2(w1, w1);
        const ulonglong2* ap = (const ulonglong2*)(&Xt[k][0]);
        #pragma unroll
        for (int p = 0; p < 8; p++) {
            ulonglong2 a = ap[p];
            a0[2 * p + 0] = fma2(a.x, ww0, a0[2 * p + 0]);
            a0[2 * p + 1] = fma2(a.y, ww0, a0[2 * p + 1]);
            a1[2 * p + 0] = fma2(a.x, ww1, a1[2 * p + 0]);
            a1[2 * p + 1] = fma2(a.y, ww1, a1[2 * p + 1]);
        }
    }
    float* o0 = g_embW0 + (size_t)v0 * 240 + j0;
    #pragma unroll
    for (int i = 0; i < 16; i++) {
        float2 v = u2f2(a0[i]);
        float2 u = u2f2(a1[i]);
        int r = 2 * i;
        if (r < rows)     { o0[(size_t)r * 240] = v.x;       o0[(size_t)r * 240 + 120] = u.x; }
        if (r + 1 < rows) { o0[(size_t)(r + 1) * 240] = v.y; o0[(size_t)(r + 1) * 240 + 120] = u.y; }
    }
}

// ---------------- gx1 GEMM: [valid rows,80] x [80,240] + bias; 2 cols/thread, 32 rows ----------------
__global__ void __launch_bounds__(128) gx1_kernel(const int* __restrict__ lens)
{
    int b = blockIdx.x;
    int t0 = blockIdx.y * 32;
    int len = lens[b];
    if (t0 >= len) return;
    int rows = len - t0; if (rows > 32) rows = 32;
    int tid = threadIdx.x;
    __shared__ __align__(16) float Xt[80][36];

    const float4* xb = (const float4*)(g_out0 + ((size_t)b * TT + t0) * 80);
    for (int idx = tid; idx < 32 * 20; idx += 128) {
        int r = idx / 20, c4 = idx % 20;
        float4 v = (r < rows) ? xb[r * 20 + c4] : make_float4(0.f, 0.f, 0.f, 0.f);
        Xt[4 * c4 + 0][r] = v.x;
        Xt[4 * c4 + 1][r] = v.y;
        Xt[4 * c4 + 2][r] = v.z;
        Xt[4 * c4 + 3][r] = v.w;
    }
    __syncthreads();
    if (tid >= 120) return;
    int j0 = tid, j1 = tid + 120;
    u64 a0[16], a1[16];
    {
        float b0 = g_bih1cat[j0], b1 = g_bih1cat[j1];
        u64 i0 = f2u2(b0, b0), i1 = f2u2(b1, b1);
        #pragma unroll
        for (int i = 0; i < 16; i++) { a0[i] = i0; a1[i] = i1; }
    }
    #pragma unroll 4
    for (int k = 0; k < 80; k++) {
        float w0 = g_Wih1T[k * 240 + j0];
        float w1 = g_Wih1T[k * 240 + j1];
        u64 ww0 = f2u2(w0, w0), ww1 = f2u2(w1, w1);
        const ulonglong2* ap = (const ulonglong2*)(&Xt[k][0]);
        #pragma unroll
        for (int p = 0; p < 8; p++) {
            ulonglong2 a = ap[p];
            a0[2 * p + 0] = fma2(a.x, ww0, a0[2 * p + 0]);
            a0[2 * p + 1] = fma2(a.y, ww0, a0[2 * p + 1]);
            a1[2 * p + 0] = fma2(a.x, ww1, a1[2 * p + 0]);
            a1[2 * p + 1] = fma2(a.y, ww1, a1[2 * p + 1]);
        }
    }
    float* o0 = g_gx1 + ((size_t)b * TT + t0) * 240 + j0;
    #pragma unroll
    for (int i = 0; i < 16; i++) {
        float2 v = u2f2(a0[i]);
        float2 u = u2f2(a1[i]);
        int r = 2 * i;
        if (r < rows)     { o0[(size_t)r * 240] = v.x;       o0[(size_t)r * 240 + 120] = u.x; }
        if (r + 1 < rows) { o0[(size_t)(r + 1) * 240] = v.y; o0[(size_t)(r + 1) * 240 + 120] = u.y; }
    }
}

// ---- shared recurrence step body: split-chain dot, MUFU acts, branch-free stores ----
#define GRU_CORE(PR, PZ, PN, QR, QZ, QN, EBASE, STRIDE_EXPR, ACT_EXTRA0, ACT_EXTRA1)        \
    {                                                                                       \
        float xr = PR, xz = PZ, xn = PN, yr = QR, yz = QZ, yn = QN;                         \
        {                                                                                   \
            const float* e_ = (EBASE) + (STRIDE_EXPR);                                      \
            PR = e_[u0]; PZ = e_[40 + u0]; PN = e_[80 + u0];                                \
            QR = e_[u1c]; QZ = e_[40 + u1c]; QN = e_[80 + u1c];                             \
        }                                                                                   \
        u64 a0a = bbu[0], a0b = 0ull;                                                       \
        u64 a1a = bbu[1], a1b = 0ull;                                                       \
        u64 a2a = bbu[2], a2b = 0ull;                                                       \
        u64 a3a = bbu[3], a3b = 0ull;                                                       \
        const ulonglong2* hq = (const ulonglong2*)hsm;                                      \
        _Pragma("unroll")                                                                   \
        for (int q = 0; q < 5; q++) {                                                       \
            ulonglong2 hA = hq[2 * q], hB = hq[2 * q + 1];                                  \
            a0a = fma2(w[0][4*q],   hA.x, a0a); a0a = fma2(w[0][4*q+1], hA.y, a0a);         \
            a0b = fma2(w[0][4*q+2], hB.x, a0b); a0b = fma2(w[0][4*q+3], hB.y, a0b);         \
            a1a = fma2(w[1][4*q],   hA.x, a1a); a1a = fma2(w[1][4*q+1], hA.y, a1a);         \
            a1b = fma2(w[1][4*q+2], hB.x, a1b); a1b = fma2(w[1][4*q+3], hB.y, a1b);         \
            a2a = fma2(w[2][4*q],   hA.x, a2a); a2a = fma2(w[2][4*q+1], hA.y, a2a);         \
            a2b = fma2(w[2][4*q+2], hB.x, a2b); a2b = fma2(w[2][4*q+3], hB.y, a2b);         \
            a3a = fma2(w[3][4*q],   hA.x, a3a); a3a = fma2(w[3][4*q+1], hA.y, a3a);         \
            a3b = fma2(w[3][4*q+2], hB.x, a3b); a3b = fma2(w[3][4*q+3], hB.y, a3b);         \
        }                                                                                   \
        float2 p0 = u2f2(add2(a0a, a0b));                                                   \
        float2 p1 = u2f2(add2(a1a, a1b));                                                   \
        float2 p2 = u2f2(add2(a2a, a2b));                                                   \
        float2 p3 = u2f2(add2(a3a, a3b));                                                   \
        float d0 = p0.x + p0.y;                                                             \
        float d1 = p1.x + p1.y;                                                             \
        float d2 = p2.x + p2.y;                                                             \
        float d3 = p3.x + p3.y;                                                             \
        float s1 = __shfl_sync(FULL, d1, (lane + 8)  & 31);                                 \
        float s2 = __shfl_sync(FULL, d2, (lane + 8)  & 31);                                 \
        float s3 = __shfl_sync(FULL, d2, (lane + 16) & 31);                                 \
        float s4 = __shfl_sync(FULL, d3, (lane + 16) & 31);                                 \
        float zv0 = (lane < 24) ? s1 : s2;                                                  \
        float nv0 = (lane < 16) ? s3 : s4;                                                  \
        {                                                                                   \
            float r = sigA(xr + d0);                                                        \
            float z = sigA(xz + zv0);                                                       \
            float n = tanhA(fmaf(r, nv0, xn));                                              \
            h0 = fmaf(z, h0 - n, n);                                                        \
            hsm[u0] = h0;                                                                   \
            ACT_EXTRA0;                                                                     \
        }                                                                                   \
        {                                                                                   \
            float r = sigA(yr + d1);                                                        \
            float z = sigA(yz + s2);                                                        \
            float n = tanhA(fmaf(r, s4, yn));                                               \
            h1 = fmaf(z, h1 - n, n);                                                        \
            hsm[h1idx] = h1;                                                                \
            ACT_EXTRA1;                                                                     \
        }                                                                                   \
        __syncwarp();                                                                       \
    }

// ---------------- Layer 0: one warp per (batch,dir); unroll-2 distance-2 prefetch ----------------
__global__ void __launch_bounds__(128) gru_layer0(
    const int* __restrict__ text, const int* __restrict__ lens,
    const float* __restrict__ bhh0f, const float* __restrict__ bhh0b)
{
    int wid = threadIdx.x >> 5, lane = threadIdx.x & 31;
    int wgid = blockIdx.x * 4 + wid;
    __shared__ int toks_s[4][TT];
    __shared__ __align__(16) float h_s[4][80];   // [0..39] h, [40..71] dead zone
    if (wgid >= 512) return;
    int* toks = toks_s[wid];
    float* hsm = h_s[wid];
    const unsigned FULL = 0xffffffffu;
    float* sinkp = g_sink + (size_t)wgid * 32 + lane;

    for (int slot = 0; slot < 2; slot++) {
        int c = slot ? (1023 - wgid) : wgid;
        int b = g_perm[c >> 1];
        int dir = c & 1;
        int len = lens[b];

        for (int i = lane; i < len; i += 32) toks[i] = text[b * TT + i];

        u64 w[4][20];
        u64 bbu[4];
        const u64* wp = (const u64*)g_Whh0P4 + (size_t)dir * 120 * 20;
        const float* bhh = dir ? bhh0b : bhh0f;
        #pragma unroll
        for (int m = 0; m < 4; m++) {
            int f = lane + 32 * m;
            if (f < 120) {
                const u64* wf = wp + f * 20;
                #pragma unroll
                for (int k2 = 0; k2 < 20; k2++) w[m][k2] = wf[k2];
                bbu[m] = f2u2(bhh[f], 0.f);
            } else {
                #pragma unroll
                for (int k2 = 0; k2 < 20; k2++) w[m][k2] = 0ull;
                bbu[m] = 0ull;
            }
        }
        hsm[lane] = 0.f;
        if (lane < 16) hsm[32 + lane] = 0.f;
        __syncwarp();

        int t0 = dir ? (len - 1) : 0;
        int td = dir ? -1 : 1;
        const float* embW = g_embW0 + dir * 120;
        int u0 = lane;
        int u1c = 32 + (lane & 7);
        bool two = (lane < 8);
        int h1idx = two ? u1c : (40 + lane);   // branch-free smem store target

        // A/C = even-step gates, B/D = odd-step gates
        float Ar, Az, An, Cr, Cz, Cn, Br, Bz, Bn, Dr, Dz, Dn;
        {
            const float* e0 = embW + (size_t)toks[t0] * 240;
            Ar = e0[u0]; Az = e0[40 + u0]; An = e0[80 + u0];
            Cr = e0[u1c]; Cz = e0[40 + u1c]; Cn = e0[80 + u1c];
            int s1i = (len > 1) ? 1 : 0;
            const float* e1 = embW + (size_t)toks[t0 + s1i * td] * 240;
            Br = e1[u0]; Bz = e1[40 + u0]; Bn = e1[80 + u0];
            Dr = e1[u1c]; Dz = e1[40 + u1c]; Dn = e1[80 + u1c];
        }
        float h0 = 0.f, h1 = 0.f;
        float* outb = g_out0 + ((size_t)b * TT + t0) * 80 + dir * 40;
        long ostep = (long)td * 80;

        for (int s = 0; s < len; s += 2) {
            {
                int sp = (s + 2 < len) ? s + 2 : len - 1;
                GRU_CORE(Ar, Az, An, Cr, Cz, Cn, embW,
                         (size_t)toks[t0 + sp * td] * 240,
                         outb[u0] = h0,
                         *(two ? (outb + u1c) : sinkp) = h1)
                outb += ostep;
            }
            if (s + 1 >= len) break;
            {
                int sp = (s + 3 < len) ? s + 3 : len - 1;
                GRU_CORE(Br, Bz, Bn, Dr, Dz, Dn, embW,
                         (size_t)toks[t0 + sp * td] * 240,
                         outb[u0] = h0,
                         *(two ? (outb + u1c) : sinkp) = h1)
                outb += ostep;
            }
        }
        float* hl = dir ? g_hb0 : g_hf0;
        hl[b * HH + u0] = h0;
        if (two) hl[b * HH + u1c] = h1;
    }
}

// ---------------- Layer 1: same shape, gx precomputed, fused pooling ----------------
__global__ void __launch_bounds__(128) gru_layer1(
    const int* __restrict__ lens,
    const float* __restrict__ bhh1f, const float* __restrict__ bhh1b)
{
    int wid = threadIdx.x >> 5, lane = threadIdx.x & 31;
    int wgid = blockIdx.x * 4 + wid;
    __shared__ __align__(16) float h_s[4][80];
    if (wgid >= 512) return;
    float* hsm = h_s[wid];
    const unsigned FULL = 0xffffffffu;

    for (int slot = 0; slot < 2; slot++) {
        int c = slot ? (1023 - wgid) : wgid;
        int b = g_perm[c >> 1];
        int dir = c & 1;
        int len = lens[b];

        u64 w[4][20];
        u64 bbu[4];
        const u64* wp = (const u64*)g_Whh1P4 + (size_t)dir * 120 * 20;
        const float* bhh = dir ? bhh1b : bhh1f;
        #pragma unroll
        for (int m = 0; m < 4; m++) {
            int f = lane + 32 * m;
            if (f < 120) {
                const u64* wf = wp + f * 20;
                #pragma unroll
                for (int k2 = 0; k2 < 20; k2++) w[m][k2] = wf[k2];
                bbu[m] = f2u2(bhh[f], 0.f);
            } else {
                #pragma unroll
                for (int k2 = 0; k2 < 20; k2++) w[m][k2] = 0ull;
                bbu[m] = 0ull;
            }
        }
        hsm[lane] = 0.f;
        if (lane < 16) hsm[32 + lane] = 0.f;
        __syncwarp();

        int t0 = dir ? (len - 1) : 0;
        int td = dir ? -1 : 1;
        const float* gxb = g_gx1 + ((size_t)b * TT) * 240 + dir * 120;
        int u0 = lane;
        int u1c = 32 + (lane & 7);
        bool two = (lane < 8);
        int h1idx = two ? u1c : (40 + lane);

        float Ar, Az, An, Cr, Cz, Cn, Br, Bz, Bn, Dr, Dz, Dn;
        {
            const float* e0 = gxb + (size_t)t0 * 240;
            Ar = e0[u0]; Az = e0[40 + u0]; An = e0[80 + u0];
            Cr = e0[u1c]; Cz = e0[40 + u1c]; Cn = e0[80 + u1c];
            int s1i = (len > 1) ? 1 : 0;
            const float* e1 = gxb + (size_t)(t0 + s1i * td) * 240;
            Br = e1[u0]; Bz = e1[40 + u0]; Bn = e1[80 + u0];
            Dr = e1[u1c]; Dz = e1[40 + u1c]; Dn = e1[80 + u1c];
        }
        float h0 = 0.f, h1 = 0.f;
        float sum0 = 0.f, max0 = -1e30f, sum1 = 0.f, max1 = -1e30f;

        for (int s = 0; s < len; s += 2) {
            {
                int sp = (s + 2 < len) ? s + 2 : len - 1;
                GRU_CORE(Ar, Az, An, Cr, Cz, Cn, gxb,
                         (size_t)(t0 + sp * td) * 240,
                         { sum0 += h0; max0 = fmaxf(max0, h0); },
                         { sum1 += h1; max1 = fmaxf(max1, h1); })
            }
            if (s + 1 >= len) break;
            {
                int sp = (s + 3 < len) ? s + 3 : len - 1;
                GRU_CORE(Br, Bz, Bn, Dr, Dz, Dn, gxb,
                         (size_t)(t0 + sp * td) * 240,
                         { sum0 += h0; max0 = fmaxf(max0, h0); },
                         { sum1 += h1; max1 = fmaxf(max1, h1); })
            }
        }
        float inv = __fdividef(1.f, (float)len);
        g_avgp[b * 80 + dir * 40 + u0] = sum0 * inv;
        g_maxp[b * 80 + dir * 40 + u0] = max0;
        float* hl = dir ? g_hb1 : g_hf1;
        hl[b * HH + u0] = h0;
        if (two) {
            g_avgp[b * 80 + dir * 40 + u1c] = sum1 * inv;
            g_maxp[b * 80 + dir * 40 + u1c] = max1;
            hl[b * HH + u1c] = h1;
        }
    }
}

// ---------------- Head: pool_cat -> fc1 -> leaky -> fc2 ----------------
__global__ void __launch_bounds__(128) fc_kernel(
    const float* __restrict__ fc1_b, const float* __restrict__ fc2_W,
    const float* __restrict__ fc2_b, float* __restrict__ out)
{
    int b = blockIdx.x, j = threadIdx.x;
    __shared__ float cat[320];
    for (int i = j; i < 320; i += 128) {
        float v;
        if (i < 40)       v = g_hb1[b * 40 + i];
        else if (i < 80)  v = g_hf1[b * 40 + (i - 40)];
        else if (i < 120) v = g_hb0[b * 40 + (i - 80)];
        else if (i < 160) v = g_hf0[b * 40 + (i - 120)];
        else if (i < 240) v = g_avgp[b * 80 + (i - 160)];
        else              v = g_maxp[b * 80 + (i - 240)];
        cat[i] = v;
    }
    __syncthreads();
    float acc = fc1_b[j];
    #pragma unroll 8
    for (int k = 0; k < 320; k++)
        acc = fmaf(g_fc1WT[k * 128 + j], cat[k], acc);
    float h = (acc >= 0.f) ? acc : 0.01f * acc;
    float p = h * fc2_W[j];
    #pragma unroll
    for (int o = 16; o > 0; o >>= 1) p += __shfl_down_sync(0xffffffffu, p, o);
    __shared__ float red[4];
    if ((j & 31) == 0) red[j >> 5] = p;
    __syncthreads();
    if (j == 0) out[b] = (red[0] + red[1] + red[2] + red[3]) + fc2_b[0];
}

// ---------------- Launch ----------------
extern "C" void kernel_launch(void* const* d_in, const int* in_sizes, int n_in,
                              void* d_out, int out_size)
{
    const int*   text     = (const int*)d_in[0];
    const int*   text_len = (const int*)d_in[1];
    const float* emb      = (const float*)d_in[2];
    const float* Wih0f = (const float*)d_in[3];
    const float* Whh0f = (const float*)d_in[4];
    const float* bih0f = (const float*)d_in[5];
    const float* bhh0f = (const float*)d_in[6];
    const float* Wih0b = (const float*)d_in[7];
    const float* Whh0b = (const float*)d_in[8];
    const float* bih0b = (const float*)d_in[9];
    const float* bhh0b = (const float*)d_in[10];
    const float* Wih1f = (const float*)d_in[11];
    const float* Whh1f = (const float*)d_in[12];
    const float* bih1f = (const float*)d_in[13];
    const float* bhh1f = (const float*)d_in[14];
    const float* Wih1b = (const float*)d_in[15];
    const float* Whh1b = (const float*)d_in[16];
    const float* bih1b = (const float*)d_in[17];
    const float* bhh1b = (const float*)d_in[18];
    const float* fc1_W = (const float*)d_in[19];
    const float* fc1_b = (const float*)d_in[20];
    const float* fc2_W = (const float*)d_in[21];
    const float* fc2_b = (const float*)d_in[22];
    float* out = (float*)d_out;

    prep_weights<<<160, 256>>>(Wih0f, Whh0f, bih0f, Wih0b, Whh0b, bih0b,
                               Wih1f, Whh1f, bih1f, Wih1b, Whh1b, bih1b, fc1_W);
    sort_kernel<<<1, BB>>>(text_len);
    embw_kernel<<<(VV + 31) / 32, 128>>>(emb);
    gru_layer0<<<148, 128>>>(text, text_len, bhh0f, bhh0b);
    gx1_kernel<<<dim3(BB, TT / 32), 128>>>(text_len);
    gru_layer1<<<148, 128>>>(text_len, bhh1f, bhh1b);
    fc_kernel<<<BB, 128>>>(fc1_b, fc2_W, fc2_b, out);
}